// round 12
// baseline (speedup 1.0000x reference)
#include <cuda_runtime.h>

// Input order (metadata): W1 b1 W2 b2 W3 b3 G1..G6 data_x func_val data_y step_size
// Output: [B, 388] float32 = [w_flat(193) | g_flat(193) | loss | improvement]

#define BDIM  128
#define WARPS 4
#define NSAMP 150
#define NITER 3            // 64 samples/iter (2 per lane), 192 slots >= 150

__constant__ float c_lr[6] = {0.001f, 0.01f, 0.05f, 0.1f, 0.5f, 1.0f};

__device__ float g_partials[16384];
__device__ float g_coef;

static __device__ __forceinline__ float clamp1e4(float v) {
    return fminf(fmaxf(v, -10000.0f), 10000.0f);
}

// Param flat layout (matches reference concat order):
//   W1 [0,40) h*4+f | b1 [40,50) | W2 [50,150) g*10+h | b2 [150,160)
//   W3 [160,190) o*10+g | b3 [190,193)

// Factor selectors; j is always a compile-time constant (fully unrolled callers)
static __device__ __forceinline__ float fA(const float (&t)[10], const float (&dh2)[10],
                                           const float (&d)[3], int j) {
    if (j < 40)  return t[j >> 2];
    if (j < 50)  return t[j - 40];
    if (j < 150) return dh2[(j - 50) / 10];
    if (j < 160) return dh2[j - 150];
    if (j < 190) return d[(j - 160) / 10];
    if (j < 193) return d[j - 190];
    return 0.0f;
}
static __device__ __forceinline__ float fB(const float (&h1)[10], const float (&h2)[10],
                                           const float4& x, int j) {
    if (j < 40) {
        const int f = j & 3;
        return f == 0 ? x.x : (f == 1 ? x.y : (f == 2 ? x.z : x.w));
    }
    if (j < 50)  return 1.0f;
    if (j < 150) return h1[(j - 50) % 10];
    if (j < 160) return 1.0f;
    if (j < 190) return h2[(j - 160) % 10];
    return 1.0f;
}

__global__ __launch_bounds__(BDIM, 3) void k_mlp(
    const float* __restrict__ W1, const float* __restrict__ B1,
    const float* __restrict__ W2, const float* __restrict__ B2,
    const float* __restrict__ W3, const float* __restrict__ B3,
    const float* __restrict__ G1, const float* __restrict__ G2,
    const float* __restrict__ G3, const float* __restrict__ G4,
    const float* __restrict__ G5, const float* __restrict__ G6,
    const float* __restrict__ dx, const float* __restrict__ fv,
    const int*   __restrict__ dy, const int*   __restrict__ ss,
    float* __restrict__ out)
{
    __shared__ float4 sx[NSAMP];
    __shared__ int    sy[NSAMP];
    __shared__ float  ws_s[WARPS][193];
    __shared__ float  swsq[WARPS];

    const int tid  = threadIdx.x;
    const int lane = tid & 31;
    const int w    = tid >> 5;
    const int b    = blockIdx.x * WARPS + w;

    for (int i = tid; i < NSAMP; i += BDIM) {
        sx[i] = reinterpret_cast<const float4*>(dx)[i];
        sy[i] = dy[i];
    }
    __syncthreads();

    float* ws   = ws_s[w];
    float* orow = out + (size_t)b * 388;

    // ---- SGD update: w = p - lr*g; clipped copy straight to output ----
    const float lr = c_lr[ss[b]];
#define UPD(P, G, OFF, CNT)                                               \
    for (int i = lane; i < CNT; i += 32) {                                \
        float v = P[(size_t)b * CNT + i] - lr * G[(size_t)b * CNT + i];   \
        ws[OFF + i] = v;                                                  \
        orow[OFF + i] = clamp1e4(v);                                      \
    }
    UPD(W1, G1, 0, 40)
    UPD(B1, G2, 40, 10)
    UPD(W2, G3, 50, 100)
    UPD(B2, G4, 150, 10)
    UPD(W3, G5, 160, 30)
    UPD(B3, G6, 190, 3)
#undef UPD
    __syncwarp();

    float acc[6];
#pragma unroll
    for (int g = 0; g < 6; ++g) acc[g] = 0.0f;
    float acc192 = 0.0f;          // j = 192 (b3[2]) handled without a full butterfly
    float loss_sum = 0.0f;

#pragma unroll 1
    for (int it = 0; it < NITER; ++it) {
        const int nA = it * 64 + lane;
        const int nB = nA + 32;
        const bool actA = (nA < NSAMP), actB = (nB < NSAMP);
        const float4 xa = sx[actA ? nA : 0];
        const float4 xb = sx[actB ? nB : 0];
        const int ya = sy[actA ? nA : 0];
        const int yb = sy[actB ? nB : 0];
        const float wNa = actA ? (1.0f / (float)NSAMP) : 0.0f;
        const float wNb = actB ? (1.0f / (float)NSAMP) : 0.0f;

        // ---- layer 1 (weights loaded once, feed both samples) ----
        float h1a[10], h1b[10];
#pragma unroll
        for (int h = 0; h < 10; ++h) {
            float za = ws[40 + h], zb = za;
            { const float wv = ws[h * 4 + 0]; za = fmaf(wv, xa.x, za); zb = fmaf(wv, xb.x, zb); }
            { const float wv = ws[h * 4 + 1]; za = fmaf(wv, xa.y, za); zb = fmaf(wv, xb.y, zb); }
            { const float wv = ws[h * 4 + 2]; za = fmaf(wv, xa.z, za); zb = fmaf(wv, xb.z, zb); }
            { const float wv = ws[h * 4 + 3]; za = fmaf(wv, xa.w, za); zb = fmaf(wv, xb.w, zb); }
            h1a[h] = fmaxf(za, 0.0f); h1b[h] = fmaxf(zb, 0.0f);
        }
        // ---- layer 2 ----
        float h2a[10], h2b[10];
#pragma unroll
        for (int g = 0; g < 10; ++g) {
            float za = ws[150 + g], zb = za;
#pragma unroll
            for (int h = 0; h < 10; ++h) {
                const float wv = ws[50 + g * 10 + h];
                za = fmaf(wv, h1a[h], za); zb = fmaf(wv, h1b[h], zb);
            }
            h2a[g] = fmaxf(za, 0.0f); h2b[g] = fmaxf(zb, 0.0f);
        }
        // ---- layer 3 ----
        float l0a = ws[190], l1a = ws[191], l2a = ws[192];
        float l0b = l0a, l1b = l1a, l2b = l2a;
#pragma unroll
        for (int g = 0; g < 10; ++g) {
            const float w0 = ws[160 + g], w1 = ws[170 + g], w2 = ws[180 + g];
            l0a = fmaf(w0, h2a[g], l0a); l0b = fmaf(w0, h2b[g], l0b);
            l1a = fmaf(w1, h2a[g], l1a); l1b = fmaf(w1, h2b[g], l1b);
            l2a = fmaf(w2, h2a[g], l2a); l2b = fmaf(w2, h2b[g], l2b);
        }
        // ---- softmax CE, both samples ----
        float da[3], db[3];
        {
            const float m  = fmaxf(l0a, fmaxf(l1a, l2a));
            const float e0 = __expf(l0a - m), e1 = __expf(l1a - m), e2 = __expf(l2a - m);
            const float s  = e0 + e1 + e2;
            const float inv = __fdividef(1.0f, s);
            const float ly = (ya == 0) ? l0a : ((ya == 1) ? l1a : l2a);
            loss_sum += actA ? (m + __logf(s) - ly) : 0.0f;
            da[0] = (e0 * inv - ((ya == 0) ? 1.0f : 0.0f)) * wNa;
            da[1] = (e1 * inv - ((ya == 1) ? 1.0f : 0.0f)) * wNa;
            da[2] = (e2 * inv - ((ya == 2) ? 1.0f : 0.0f)) * wNa;
        }
        {
            const float m  = fmaxf(l0b, fmaxf(l1b, l2b));
            const float e0 = __expf(l0b - m), e1 = __expf(l1b - m), e2 = __expf(l2b - m);
            const float s  = e0 + e1 + e2;
            const float inv = __fdividef(1.0f, s);
            const float ly = (yb == 0) ? l0b : ((yb == 1) ? l1b : l2b);
            loss_sum += actB ? (m + __logf(s) - ly) : 0.0f;
            db[0] = (e0 * inv - ((yb == 0) ? 1.0f : 0.0f)) * wNb;
            db[1] = (e1 * inv - ((yb == 1) ? 1.0f : 0.0f)) * wNb;
            db[2] = (e2 * inv - ((yb == 2) ? 1.0f : 0.0f)) * wNb;
        }
        // ---- dh2 = relu' * (W3^T d) ----
        float dh2a[10], dh2b[10];
#pragma unroll
        for (int g = 0; g < 10; ++g) {
            const float w0 = ws[160 + g], w1 = ws[170 + g], w2 = ws[180 + g];
            float ta = da[0] * w0; ta = fmaf(da[1], w1, ta); ta = fmaf(da[2], w2, ta);
            float tb = db[0] * w0; tb = fmaf(db[1], w1, tb); tb = fmaf(db[2], w2, tb);
            dh2a[g] = (h2a[g] > 0.0f) ? ta : 0.0f;
            dh2b[g] = (h2b[g] > 0.0f) ? tb : 0.0f;
        }
        // ---- t = relu' * (W2^T dh2) ----
        float t_a[10], t_b[10];
#pragma unroll
        for (int h = 0; h < 10; ++h) {
            float ta = 0.0f, tb = 0.0f;
#pragma unroll
            for (int g = 0; g < 10; ++g) {
                const float wv = ws[50 + g * 10 + h];
                ta = fmaf(dh2a[g], wv, ta); tb = fmaf(dh2b[g], wv, tb);
            }
            t_a[h] = (h1a[h] > 0.0f) ? ta : 0.0f;
            t_b[h] = (h1b[h] > 0.0f) ? tb : 0.0f;
        }

        // ---- per-iter gradient reduction: register products + butterfly ----
#pragma unroll
        for (int grp = 0; grp < 6; ++grp) {
            float r[32];
#pragma unroll
            for (int k = 0; k < 32; ++k) {
                const int j = grp * 32 + k;
                const float pa = fA(t_a, dh2a, da, j) * fB(h1a, h2a, xa, j);
                r[k] = fmaf(fA(t_b, dh2b, db, j), fB(h1b, h2b, xb, j), pa);
            }
#pragma unroll
            for (int st = 0; st < 5; ++st) {
                const int half = 16 >> st;
                const bool up = (lane & half) != 0;
#pragma unroll
                for (int i = 0; i < 16; ++i) {
                    if (i < half) {
                        const float a2 = r[i], b2 = r[i + half];
                        const float keep = up ? b2 : a2;
                        const float send = up ? a2 : b2;
                        r[i] = keep + __shfl_xor_sync(0xffffffffu, send, half);
                    }
                }
            }
            acc[grp] += r[0];
        }
        // j = 192: single entry, plain tree reduce
        {
            float p = da[2] + db[2];
#pragma unroll
            for (int m2 = 16; m2; m2 >>= 1)
                p += __shfl_xor_sync(0xffffffffu, p, m2);
            acc192 += p;
        }
    }

    // ---- loss reduce ----
#pragma unroll
    for (int m2 = 16; m2; m2 >>= 1)
        loss_sum += __shfl_xor_sync(0xffffffffu, loss_sum, m2);
    const float loss_b = loss_sum * (1.0f / (float)NSAMP);

    // ---- store grads (unscaled) + per-lane sumsq ----
    float sumsq = 0.0f;
#pragma unroll
    for (int g = 0; g < 6; ++g) {
        const int j = g * 32 + lane;
        orow[193 + j] = acc[g];
        sumsq = fmaf(acc[g], acc[g], sumsq);
    }
    if (lane == 0) {
        orow[193 + 192] = acc192;
        sumsq = fmaf(acc192, acc192, sumsq);
    }
#pragma unroll
    for (int m2 = 16; m2; m2 >>= 1)
        sumsq += __shfl_xor_sync(0xffffffffu, sumsq, m2);

    if (lane == 0) {
        orow[386] = loss_b;
        orow[387] = clamp1e4(fv[b] - loss_b);
        swsq[w] = sumsq;
    }
    __syncthreads();
    if (tid == 0)
        g_partials[blockIdx.x] = swsq[0] + swsq[1] + swsq[2] + swsq[3];
}

__global__ void k_norm(int nparts) {
    __shared__ float sh[32];
    float s = 0.0f;
    for (int i = threadIdx.x; i < nparts; i += blockDim.x) s += g_partials[i];
#pragma unroll
    for (int m = 16; m; m >>= 1) s += __shfl_xor_sync(0xffffffffu, s, m);
    if ((threadIdx.x & 31) == 0) sh[threadIdx.x >> 5] = s;
    __syncthreads();
    if (threadIdx.x < 32) {
        float t = (threadIdx.x < (blockDim.x >> 5)) ? sh[threadIdx.x] : 0.0f;
#pragma unroll
        for (int m = 16; m; m >>= 1) t += __shfl_xor_sync(0xffffffffu, t, m);
        if (threadIdx.x == 0) {
            const float tn = sqrtf(t);
            g_coef = fminf(1.0f, 10.0f / (tn + 1e-6f));
        }
    }
}

__global__ void k_scale(float* __restrict__ out, int B) {
    const int idx = blockIdx.x * blockDim.x + threadIdx.x;
    const int total = B * 193;
    if (idx < total) {
        const int b = idx / 193;
        const int j = idx - b * 193;
        out[(size_t)b * 388 + 193 + j] *= g_coef;
    }
}

extern "C" void kernel_launch(void* const* d_in, const int* in_sizes, int n_in,
                              void* d_out, int out_size)
{
    const float* W1 = (const float*)d_in[0];
    const float* B1 = (const float*)d_in[1];
    const float* W2 = (const float*)d_in[2];
    const float* B2 = (const float*)d_in[3];
    const float* W3 = (const float*)d_in[4];
    const float* B3 = (const float*)d_in[5];
    const float* G1 = (const float*)d_in[6];
    const float* G2 = (const float*)d_in[7];
    const float* G3 = (const float*)d_in[8];
    const float* G4 = (const float*)d_in[9];
    const float* G5 = (const float*)d_in[10];
    const float* G6 = (const float*)d_in[11];
    const float* dx = (const float*)d_in[12];
    const float* fv = (const float*)d_in[13];
    const int*   dy = (const int*)d_in[14];
    const int*   ss = (const int*)d_in[15];
    float* out = (float*)d_out;

    const int B = in_sizes[13];          // func_val is [B]
    const int grid1 = B / WARPS;         // 8192 for B=32768

    k_mlp<<<grid1, BDIM>>>(W1, B1, W2, B2, W3, B3,
                           G1, G2, G3, G4, G5, G6,
                           dx, fv, dy, ss, out);
    k_norm<<<1, 1024>>>(grid1);
    const int total = B * 193;
    k_scale<<<(total + 255) / 256, 256>>>(out, B);
}